// round 12
// baseline (speedup 1.0000x reference)
#include <cuda_runtime.h>
#include <cstdint>

// GRU_20031727468931: 2-layer GRU, T=16384, IN=14, H=100, out = FC(h2[T-1]).
// Round 12: R11 + branch-free gate tails. Gate math runs in all compute lanes;
// stores become inline-asm predicated @p st.shared.f32 at fixed addresses
// (removes BSSY/BSYNC reconvergence from the recurrence chain).

#define T_STEPS 16384
#define IN_DIM  14
#define H_DIM   100
#define NT      256    // warps 0-6 compute (200 active lanes), warp 7 bookkeeping

#define R_L0 0
#define R_GI 1
#define R_L1 2

#define NSLOT    8
#define SLOT_F   304u                 // floats per slot (16B-aligned stride)
#define SLOT_B   (SLOT_F * 4u)        // 1216 bytes
#define H_BYTES  416u                 // 104 floats (padded h layout)
#define G_BYTES  1200u                // 300 floats

typedef unsigned long long u64;

__device__ float g_gi0[T_STEPS * 300];   // precomputed x @ W_ih0^T + b_ih0

struct __align__(16) SmemLayout {
    u64 bar_full[NSLOT];               // 64 B
    u64 bar_empty[NSLOT];              // 64 B  -> arrays below stay 16B-aligned
    alignas(16) float h_s[2][104];     // padded: value i at index i + (i>=50 ? 2 : 0)
    alignas(16) float inbuf[NSLOT][SLOT_F];
    alignas(16) float outbuf[NSLOT][SLOT_F];
    alignas(16) float red[104];
};

__device__ __forceinline__ uint32_t s2u(const void* p) {
    uint32_t a;
    asm("{.reg .u64 t; cvta.to.shared.u64 t, %1; cvt.u32.u64 %0, t;}" : "=r"(a) : "l"(p));
    return a;
}
__device__ __forceinline__ uint32_t mapa_u32(uint32_t a, uint32_t rank) {
    uint32_t r;
    asm("mapa.shared::cluster.u32 %0, %1, %2;" : "=r"(r) : "r"(a), "r"(rank));
    return r;
}
__device__ __forceinline__ void mbar_init(uint32_t a, uint32_t n) {
    asm volatile("mbarrier.init.shared.b64 [%0], %1;" :: "r"(a), "r"(n) : "memory");
}
__device__ __forceinline__ void mbar_arrive_local(uint32_t a) {
    asm volatile("mbarrier.arrive.shared.b64 _, [%0];" :: "r"(a) : "memory");
}
__device__ __forceinline__ void mbar_expect_tx(uint32_t a, uint32_t bytes) {
    asm volatile("mbarrier.arrive.expect_tx.shared.b64 _, [%0], %1;"
                 :: "r"(a), "r"(bytes) : "memory");
}
__device__ __forceinline__ void arrive_rel_cluster(uint32_t a) {
    asm volatile("mbarrier.arrive.release.cluster.shared::cluster.b64 _, [%0];"
                 :: "r"(a) : "memory");
}
__device__ __forceinline__ void wait_par_acq(uint32_t a, uint32_t parity) {
    asm volatile(
        "{\n\t.reg .pred P;\n"
        "W_%=:\n\t"
        "mbarrier.try_wait.parity.acquire.cluster.shared::cta.b64 P, [%0], %1;\n\t"
        "@!P bra W_%=;\n\t}"
        :: "r"(a), "r"(parity) : "memory");
}
__device__ __forceinline__ void fence_pa() {
    asm volatile("fence.proxy.async.shared::cta;" ::: "memory");
}
__device__ __forceinline__ void bulk_copy_cluster(uint32_t dst_dsmem, uint32_t src_local,
                                                  uint32_t bytes, uint32_t rem_mbar) {
    asm volatile(
        "cp.async.bulk.shared::cluster.shared::cta.mbarrier::complete_tx::bytes "
        "[%0], [%1], %2, [%3];"
        :: "r"(dst_dsmem), "r"(src_local), "r"(bytes), "r"(rem_mbar) : "memory");
}
__device__ __forceinline__ void bar_sync_cnt(int name, int cnt) {
    asm volatile("bar.sync %0, %1;" :: "r"(name), "r"(cnt) : "memory");
}
__device__ __forceinline__ void bar_arrive_cnt(int name, int cnt) {
    asm volatile("bar.arrive %0, %1;" :: "r"(name), "r"(cnt) : "memory");
}
// predicated shared store: @p st.shared.f32 — no BSSY/BSYNC
__device__ __forceinline__ void sts_pred(uint32_t addr, float v, uint32_t predv) {
    asm volatile(
        "{\n\t.reg .pred p;\n\t"
        "setp.ne.u32 p, %2, 0;\n\t"
        "@p st.shared.f32 [%0], %1;\n\t}"
        :: "r"(addr), "f"(v), "r"(predv) : "memory");
}
__device__ __forceinline__ void fma2(u64& acc, u64 w, u64 h) {
    asm("fma.rn.f32x2 %0, %1, %2, %0;" : "+l"(acc) : "l"(w), "l"(h));
}
__device__ __forceinline__ float unpack_sum(u64 a, u64 b) {
    float l0, h0, l1, h1;
    asm("mov.b64 {%0,%1}, %2;" : "=f"(l0), "=f"(h0) : "l"(a));
    asm("mov.b64 {%0,%1}, %2;" : "=f"(l1), "=f"(h1) : "l"(b));
    return (l0 + l1) + (h0 + h1);
}
__device__ __forceinline__ float tanha(float x) {
    float y;
    asm("tanh.approx.f32 %0, %1;" : "=f"(y) : "f"(x));
    return y;
}
__device__ __forceinline__ float sigt(float x) {       // sigmoid via tanh.approx
    return fmaf(0.5f, tanha(0.5f * x), 0.5f);
}
__device__ __forceinline__ void cluster_sync_all() {
    asm volatile("barrier.cluster.arrive.aligned;" ::: "memory");
    asm volatile("barrier.cluster.wait.aligned;" ::: "memory");
}

// 3 simultaneous half-row dots sharing one h half-vector (50 floats, 16B-aligned).
__device__ __forceinline__ void dot3(const u64* __restrict__ w0,
                                     const u64* __restrict__ w1,
                                     const u64* __restrict__ w2,
                                     const float* __restrict__ hbase,
                                     float& s0, float& s1, float& s2) {
    const ulonglong2* hp = (const ulonglong2*)hbase;
    u64 a0 = 0, b0 = 0, a1 = 0, b1 = 0, a2 = 0, b2 = 0;
#pragma unroll
    for (int j = 0; j < 12; j++) {
        ulonglong2 hv = hp[j];
        fma2(a0, w0[2 * j], hv.x);  fma2(b0, w0[2 * j + 1], hv.y);
        fma2(a1, w1[2 * j], hv.x);  fma2(b1, w1[2 * j + 1], hv.y);
        fma2(a2, w2[2 * j], hv.x);  fma2(b2, w2[2 * j + 1], hv.y);
    }
    u64 htail = ((const u64*)hbase)[24];
    fma2(a0, w0[24], htail);
    fma2(a1, w1[24], htail);
    fma2(a2, w2[24], htail);
    s0 = unpack_sum(a0, b0);
    s1 = unpack_sum(a1, b1);
    s2 = unpack_sum(a2, b2);
}

__device__ __forceinline__ void load_w3(const float* __restrict__ W, int p, int half,
                                        u64* w0, u64* w1, u64* w2) {
    const u64* g0 = (const u64*)(W + (p)       * H_DIM + half * 50);
    const u64* g1 = (const u64*)(W + (p + 100) * H_DIM + half * 50);
    const u64* g2 = (const u64*)(W + (p + 200) * H_DIM + half * 50);
#pragma unroll
    for (int j = 0; j < 25; j++) { w0[j] = g0[j]; w1[j] = g1[j]; w2[j] = g2[j]; }
}

// ---------------- precompute: gi0[t][g] = x[t]·W_ih0[g] + b_ih0[g] ----------------
__global__ void gi0_kernel(const float* __restrict__ x,
                           const float* __restrict__ w_ih0,
                           const float* __restrict__ b_ih0) {
    __shared__ float xs[IN_DIM];
    int t = blockIdx.x;
    int g = threadIdx.x;
    if (g < IN_DIM) xs[g] = x[t * IN_DIM + g];
    __syncthreads();
    if (g < 300) {
        float acc = b_ih0[g];
        const float* wr = w_ih0 + g * IN_DIM;
#pragma unroll
        for (int k = 0; k < IN_DIM; k++) acc = fmaf(wr[k], xs[k], acc);
        g_gi0[t * 300 + g] = acc;
    }
}

// ---------------- main cluster kernel ----------------
__global__ void __launch_bounds__(NT, 1) __cluster_dims__(4, 1, 1)
gru_cluster_kernel(const float* __restrict__ w_hh0, const float* __restrict__ b_hh0,
                   const float* __restrict__ w_ih1, const float* __restrict__ w_hh1,
                   const float* __restrict__ b_ih1, const float* __restrict__ b_hh1,
                   const float* __restrict__ fc_w,  const float* __restrict__ fc_b,
                   float* __restrict__ out)
{
    __shared__ SmemLayout sm;
    uint32_t rank;
    asm("mov.u32 %0, %%cluster_ctarank;" : "=r"(rank));
    const int tid = threadIdx.x;

    const uint32_t a_full  = s2u(&sm.bar_full[0]);
    const uint32_t a_empty = s2u(&sm.bar_empty[0]);
    const uint32_t a_inbuf = s2u(&sm.inbuf[0][0]);
    const uint32_t a_out   = s2u(&sm.outbuf[0][0]);
    const uint32_t a_hbase = s2u(&sm.h_s[0][0]);

    if (tid == 0) {
#pragma unroll
        for (int i = 0; i < NSLOT; i++) {
            mbar_init(a_full  + 8u * i, 1);
            mbar_init(a_empty + 8u * i, 1);
            mbar_arrive_local(a_empty + 8u * i);   // pre-grant credit (phase 0)
        }
        if (rank == R_GI) {
#pragma unroll
            for (int i = 0; i < NSLOT; i++) mbar_expect_tx(a_full + 8u * i, H_BYTES);
        } else if (rank == R_L1) {
#pragma unroll
            for (int i = 0; i < NSLOT; i++) mbar_expect_tx(a_full + 8u * i, G_BYTES);
        }
    }
    if (tid < 104) { sm.h_s[0][tid] = 0.0f; sm.h_s[1][tid] = 0.0f; }
    __syncthreads();
    cluster_sync_all();

    const int  idx  = (tid < 200) ? tid : 199;
    const int  p    = idx >> 1;          // pair id = gate row (0..99)
    const int  half = idx & 1;
    const bool lead = ((tid & 1) == 0) && (tid < 200);
    const uint32_t leadp = lead ? 1u : 0u;
    const int  pos  = p + (p >= 50 ? 2 : 0);   // padded h index

    if (rank == R_L0) {
        const uint32_t rem_inbuf = mapa_u32(a_inbuf, R_GI);
        const uint32_t rem_full  = mapa_u32(a_full,  R_GI);

        if (tid >= 224) {
            // ---- bookkeeping warp ----
            if (tid == 224) {   // certify slots for steps 0,1 (empty pre-granted ph0)
                wait_par_acq(a_empty + 0, 0);
                wait_par_acq(a_empty + 8, 0);
            }
            bar_arrive_cnt(1, NT);            // enable compute step 0
            for (int t = 0; t < T_STEPS; ++t) {
                bar_sync_cnt(2, NT);          // compute finished step t
                bar_arrive_cnt(1, NT);        // enable compute step t+1
                if (tid == 224) {
                    const int s = t & (NSLOT - 1);
                    fence_pa();
                    bulk_copy_cluster(rem_inbuf + (uint32_t)s * SLOT_B,
                                      a_out + (uint32_t)s * SLOT_B,
                                      H_BYTES, rem_full + 8u * s);
                    if (t + 2 < T_STEPS) {
                        const int sn = (t + 2) & (NSLOT - 1);
                        wait_par_acq(a_empty + 8u * sn,
                                     (uint32_t)(((t + 2) >> 3) & 1));
                    }
                }
            }
        } else {
            // ---- compute warps ----
            u64 w0[25], w1[25], w2[25];
            load_w3(w_hh0, p, half, w0, w1, w2);
            const float bh0 = b_hh0[p], bh1 = b_hh0[p + 100], bh2 = b_hh0[p + 200];
            float gc0 = g_gi0[p], gc1 = g_gi0[p + 100], gc2 = g_gi0[p + 200];
            float h_prev = 0.f;
            const uint32_t a_h_pos  = a_hbase + (uint32_t)pos * 4u;   // h_s[0][pos]
            const uint32_t a_ob_pos = a_out + (uint32_t)pos * 4u;     // outbuf[0][pos]

            for (int t = 0; t < T_STEPS; ++t) {
                const int s = t & (NSLOT - 1);
                bar_sync_cnt(1, NT);   // slot s certified free; h_s(t-1) visible

                int tn = (t + 1 < T_STEPS) ? t + 1 : t;
                float gn0 = g_gi0[tn * 300 + p];
                float gn1 = g_gi0[tn * 300 + p + 100];
                float gn2 = g_gi0[tn * 300 + p + 200];

                const int buf = t & 1;
                float s0, s1, s2;
                dot3(w0, w1, w2, &sm.h_s[buf][half * 52], s0, s1, s2);
                float o0 = __shfl_down_sync(0xFFFFFFFFu, s0, 1);
                float o1 = __shfl_down_sync(0xFFFFFFFFu, s1, 1);
                float o2 = __shfl_down_sync(0xFFFFFFFFu, s2, 1);

                // branch-free gates: all lanes compute, only leads store
                float rr = sigt(gc0 + s0 + o0 + bh0);
                float zz = sigt(gc1 + s1 + o1 + bh1);
                float nn = tanha(gc2 + rr * (s2 + o2 + bh2));
                float hn = nn + zz * (h_prev - nn);
                h_prev = hn;
                sts_pred(a_h_pos + (uint32_t)((buf ^ 1) * 416), hn, leadp);
                sts_pred(a_ob_pos + (uint32_t)s * SLOT_B, hn, leadp);

                gc0 = gn0; gc1 = gn1; gc2 = gn2;
                bar_arrive_cnt(2, NT);   // step t done
            }
        }
    } else if (rank == R_GI) {
        const uint32_t rem_empty_L0 = mapa_u32(a_empty, R_L0);
        const uint32_t rem_inbuf_L1 = mapa_u32(a_inbuf, R_L1);
        const uint32_t rem_full_L1  = mapa_u32(a_full,  R_L1);

        if (tid >= 224) {
            if (tid == 224) {   // certify steps 0,1: data arrived + slot free
                wait_par_acq(a_full + 0, 0);
                wait_par_acq(a_full + 8, 0);
                wait_par_acq(a_empty + 0, 0);
                wait_par_acq(a_empty + 8, 0);
            }
            bar_arrive_cnt(1, NT);
            for (int t = 0; t < T_STEPS; ++t) {
                bar_sync_cnt(2, NT);
                bar_arrive_cnt(1, NT);
                if (tid == 224) {
                    const int s = t & (NSLOT - 1);
                    mbar_expect_tx(a_full + 8u * s, H_BYTES);   // re-arm consumed slot
                    arrive_rel_cluster(rem_empty_L0 + 8u * s);  // credit L0
                    fence_pa();
                    bulk_copy_cluster(rem_inbuf_L1 + (uint32_t)s * SLOT_B,
                                      a_out + (uint32_t)s * SLOT_B,
                                      G_BYTES, rem_full_L1 + 8u * s);
                    if (t + 2 < T_STEPS) {
                        const int sn = (t + 2) & (NSLOT - 1);
                        const uint32_t pn = (uint32_t)(((t + 2) >> 3) & 1);
                        wait_par_acq(a_full  + 8u * sn, pn);   // h0[t+2]
                        wait_par_acq(a_empty + 8u * sn, pn);   // L1 freed slot
                    }
                }
            }
        } else {
            u64 w0[25], w1[25], w2[25];
            load_w3(w_ih1, p, half, w0, w1, w2);
            const float bi0 = b_ih1[p], bi1 = b_ih1[p + 100], bi2 = b_ih1[p + 200];
            const uint32_t a_ob_p = a_out + (uint32_t)p * 4u;

            for (int t = 0; t < T_STEPS; ++t) {
                const int s = t & (NSLOT - 1);
                bar_sync_cnt(1, NT);   // inbuf[s] full, outbuf[s] free

                float s0, s1, s2;
                dot3(w0, w1, w2, &sm.inbuf[s][half * 52], s0, s1, s2);
                float o0 = __shfl_down_sync(0xFFFFFFFFu, s0, 1);
                float o1 = __shfl_down_sync(0xFFFFFFFFu, s1, 1);
                float o2 = __shfl_down_sync(0xFFFFFFFFu, s2, 1);
                float v0 = s0 + o0 + bi0;
                float v1 = s1 + o1 + bi1;
                float v2 = s2 + o2 + bi2;
                const uint32_t base = a_ob_p + (uint32_t)s * SLOT_B;
                sts_pred(base,        v0, leadp);
                sts_pred(base + 400u, v1, leadp);   // +100 floats
                sts_pred(base + 800u, v2, leadp);   // +200 floats
                bar_arrive_cnt(2, NT);
            }
        }
    } else if (rank == R_L1) {
        const uint32_t rem_empty_GI = mapa_u32(a_empty, R_GI);

        if (tid >= 224) {
            if (tid == 224) {   // certify steps 0,1
                wait_par_acq(a_full + 0, 0);
                wait_par_acq(a_full + 8, 0);
            }
            bar_arrive_cnt(1, NT);
            for (int t = 0; t < T_STEPS; ++t) {
                bar_sync_cnt(2, NT);
                bar_arrive_cnt(1, NT);
                if (tid == 224) {
                    const int s = t & (NSLOT - 1);
                    mbar_expect_tx(a_full + 8u * s, G_BYTES);   // re-arm
                    arrive_rel_cluster(rem_empty_GI + 8u * s);  // credit GI
                    if (t + 2 < T_STEPS) {
                        const int sn = (t + 2) & (NSLOT - 1);
                        wait_par_acq(a_full + 8u * sn,
                                     (uint32_t)(((t + 2) >> 3) & 1));  // gi1[t+2]
                    }
                }
            }
        } else {
            u64 w0[25], w1[25], w2[25];
            load_w3(w_hh1, p, half, w0, w1, w2);
            const float bh0 = b_hh1[p], bh1 = b_hh1[p + 100], bh2 = b_hh1[p + 200];
            float h_prev = 0.f;
            const uint32_t a_h_pos = a_hbase + (uint32_t)pos * 4u;

            for (int t = 0; t < T_STEPS; ++t) {
                const int s = t & (NSLOT - 1);
                bar_sync_cnt(1, NT);   // inbuf[s] full; h_s(t-1) visible

                // prefetch gate inputs early (hide LDS latency under dot)
                float gir = sm.inbuf[s][p];
                float giz = sm.inbuf[s][p + 100];
                float gin = sm.inbuf[s][p + 200];

                const int buf = t & 1;
                float s0, s1, s2;
                dot3(w0, w1, w2, &sm.h_s[buf][half * 52], s0, s1, s2);
                float o0 = __shfl_down_sync(0xFFFFFFFFu, s0, 1);
                float o1 = __shfl_down_sync(0xFFFFFFFFu, s1, 1);
                float o2 = __shfl_down_sync(0xFFFFFFFFu, s2, 1);

                float rr = sigt(gir + s0 + o0 + bh0);
                float zz = sigt(giz + s1 + o1 + bh1);
                float nn = tanha(gin + rr * (s2 + o2 + bh2));
                float hn = nn + zz * (h_prev - nn);
                h_prev = hn;
                sts_pred(a_h_pos + (uint32_t)((buf ^ 1) * 416), hn, leadp);
                bar_arrive_cnt(2, NT);
            }
        }
        __syncthreads();
        if (tid < 100) sm.red[tid] = sm.h_s[0][tid + (tid >= 50 ? 2 : 0)] * fc_w[tid];
        __syncthreads();
        if (tid == 0) {
            float sv = fc_b[0];
            for (int j = 0; j < 100; j++) sv += sm.red[j];
            out[0] = sv;
        }
    }
    cluster_sync_all();
}

extern "C" void kernel_launch(void* const* d_in, const int* in_sizes, int n_in,
                              void* d_out, int out_size) {
    const float* x     = (const float*)d_in[0];
    const float* w_ih0 = (const float*)d_in[1];
    const float* w_hh0 = (const float*)d_in[2];
    const float* b_ih0 = (const float*)d_in[3];
    const float* b_hh0 = (const float*)d_in[4];
    const float* w_ih1 = (const float*)d_in[5];
    const float* w_hh1 = (const float*)d_in[6];
    const float* b_ih1 = (const float*)d_in[7];
    const float* b_hh1 = (const float*)d_in[8];
    const float* fc_w  = (const float*)d_in[9];
    const float* fc_b  = (const float*)d_in[10];
    float* out = (float*)d_out;

    gi0_kernel<<<T_STEPS, 320>>>(x, w_ih0, b_ih0);
    gru_cluster_kernel<<<4, NT>>>(w_hh0, b_hh0, w_ih1, w_hh1,
                                  b_ih1, b_hh1, fc_w, fc_b, out);
}

// round 13
// speedup vs baseline: 1.1933x; 1.1933x over previous
#include <cuda_runtime.h>
#include <cstdint>

// GRU_20031727468931: 2-layer GRU, T=16384, IN=14, H=100, out = FC(h2[T-1]).
// Round 13: R11 (best, 6068us) + (a) suspend-time hint on mbarrier retry loop
// (HW sleep, no issue-slot theft while polling) + (b) bookkeeping warp moved to
// warp 0 (lowest arbiter priority; hi-wid-first arbiter favors compute warps).
// Gate tail stays lead-only `if` (R9/R12 proved all-lane gates regress).

#define T_STEPS 16384
#define IN_DIM  14
#define H_DIM   100
#define NT      256    // warp 0 bookkeeping, warps 1-7 compute (200 active lanes)

#define R_L0 0
#define R_GI 1
#define R_L1 2

#define NSLOT    8
#define SLOT_F   304u                 // floats per slot (16B-aligned stride)
#define SLOT_B   (SLOT_F * 4u)        // 1216 bytes
#define H_BYTES  416u                 // 104 floats (padded h layout)
#define G_BYTES  1200u                // 300 floats

typedef unsigned long long u64;

__device__ float g_gi0[T_STEPS * 300];   // precomputed x @ W_ih0^T + b_ih0

struct __align__(16) SmemLayout {
    u64 bar_full[NSLOT];               // 64 B
    u64 bar_empty[NSLOT];              // 64 B  -> arrays below stay 16B-aligned
    alignas(16) float h_s[2][104];     // padded: value i at index i + (i>=50 ? 2 : 0)
    alignas(16) float inbuf[NSLOT][SLOT_F];
    alignas(16) float outbuf[NSLOT][SLOT_F];
    alignas(16) float red[104];
};

__device__ __forceinline__ uint32_t s2u(const void* p) {
    uint32_t a;
    asm("{.reg .u64 t; cvta.to.shared.u64 t, %1; cvt.u32.u64 %0, t;}" : "=r"(a) : "l"(p));
    return a;
}
__device__ __forceinline__ uint32_t mapa_u32(uint32_t a, uint32_t rank) {
    uint32_t r;
    asm("mapa.shared::cluster.u32 %0, %1, %2;" : "=r"(r) : "r"(a), "r"(rank));
    return r;
}
__device__ __forceinline__ void mbar_init(uint32_t a, uint32_t n) {
    asm volatile("mbarrier.init.shared.b64 [%0], %1;" :: "r"(a), "r"(n) : "memory");
}
__device__ __forceinline__ void mbar_arrive_local(uint32_t a) {
    asm volatile("mbarrier.arrive.shared.b64 _, [%0];" :: "r"(a) : "memory");
}
__device__ __forceinline__ void mbar_expect_tx(uint32_t a, uint32_t bytes) {
    asm volatile("mbarrier.arrive.expect_tx.shared.b64 _, [%0], %1;"
                 :: "r"(a), "r"(bytes) : "memory");
}
__device__ __forceinline__ void arrive_rel_cluster(uint32_t a) {
    asm volatile("mbarrier.arrive.release.cluster.shared::cluster.b64 _, [%0];"
                 :: "r"(a) : "memory");
}
// parity wait with HW-sleep suspend hint in the retry loop (no issue-slot spin)
__device__ __forceinline__ void wait_par_acq(uint32_t a, uint32_t parity) {
    asm volatile(
        "{\n\t.reg .pred P;\n"
        "W_%=:\n\t"
        "mbarrier.try_wait.parity.acquire.cluster.shared::cta.b64 P, [%0], %1, 0x989680;\n\t"
        "@!P bra W_%=;\n\t}"
        :: "r"(a), "r"(parity) : "memory");
}
__device__ __forceinline__ void fence_pa() {
    asm volatile("fence.proxy.async.shared::cta;" ::: "memory");
}
__device__ __forceinline__ void bulk_copy_cluster(uint32_t dst_dsmem, uint32_t src_local,
                                                  uint32_t bytes, uint32_t rem_mbar) {
    asm volatile(
        "cp.async.bulk.shared::cluster.shared::cta.mbarrier::complete_tx::bytes "
        "[%0], [%1], %2, [%3];"
        :: "r"(dst_dsmem), "r"(src_local), "r"(bytes), "r"(rem_mbar) : "memory");
}
__device__ __forceinline__ void bar_sync_cnt(int name, int cnt) {
    asm volatile("bar.sync %0, %1;" :: "r"(name), "r"(cnt) : "memory");
}
__device__ __forceinline__ void bar_arrive_cnt(int name, int cnt) {
    asm volatile("bar.arrive %0, %1;" :: "r"(name), "r"(cnt) : "memory");
}
__device__ __forceinline__ void fma2(u64& acc, u64 w, u64 h) {
    asm("fma.rn.f32x2 %0, %1, %2, %0;" : "+l"(acc) : "l"(w), "l"(h));
}
__device__ __forceinline__ float unpack_sum(u64 a, u64 b) {
    float l0, h0, l1, h1;
    asm("mov.b64 {%0,%1}, %2;" : "=f"(l0), "=f"(h0) : "l"(a));
    asm("mov.b64 {%0,%1}, %2;" : "=f"(l1), "=f"(h1) : "l"(b));
    return (l0 + l1) + (h0 + h1);
}
__device__ __forceinline__ float tanha(float x) {
    float y;
    asm("tanh.approx.f32 %0, %1;" : "=f"(y) : "f"(x));
    return y;
}
__device__ __forceinline__ float sigt(float x) {       // sigmoid via tanh.approx
    return fmaf(0.5f, tanha(0.5f * x), 0.5f);
}
__device__ __forceinline__ void cluster_sync_all() {
    asm volatile("barrier.cluster.arrive.aligned;" ::: "memory");
    asm volatile("barrier.cluster.wait.aligned;" ::: "memory");
}

// 3 simultaneous half-row dots sharing one h half-vector (50 floats, 16B-aligned).
__device__ __forceinline__ void dot3(const u64* __restrict__ w0,
                                     const u64* __restrict__ w1,
                                     const u64* __restrict__ w2,
                                     const float* __restrict__ hbase,
                                     float& s0, float& s1, float& s2) {
    const ulonglong2* hp = (const ulonglong2*)hbase;
    u64 a0 = 0, b0 = 0, a1 = 0, b1 = 0, a2 = 0, b2 = 0;
#pragma unroll
    for (int j = 0; j < 12; j++) {
        ulonglong2 hv = hp[j];
        fma2(a0, w0[2 * j], hv.x);  fma2(b0, w0[2 * j + 1], hv.y);
        fma2(a1, w1[2 * j], hv.x);  fma2(b1, w1[2 * j + 1], hv.y);
        fma2(a2, w2[2 * j], hv.x);  fma2(b2, w2[2 * j + 1], hv.y);
    }
    u64 htail = ((const u64*)hbase)[24];
    fma2(a0, w0[24], htail);
    fma2(a1, w1[24], htail);
    fma2(a2, w2[24], htail);
    s0 = unpack_sum(a0, b0);
    s1 = unpack_sum(a1, b1);
    s2 = unpack_sum(a2, b2);
}

__device__ __forceinline__ void load_w3(const float* __restrict__ W, int p, int half,
                                        u64* w0, u64* w1, u64* w2) {
    const u64* g0 = (const u64*)(W + (p)       * H_DIM + half * 50);
    const u64* g1 = (const u64*)(W + (p + 100) * H_DIM + half * 50);
    const u64* g2 = (const u64*)(W + (p + 200) * H_DIM + half * 50);
#pragma unroll
    for (int j = 0; j < 25; j++) { w0[j] = g0[j]; w1[j] = g1[j]; w2[j] = g2[j]; }
}

// ---------------- precompute: gi0[t][g] = x[t]·W_ih0[g] + b_ih0[g] ----------------
__global__ void gi0_kernel(const float* __restrict__ x,
                           const float* __restrict__ w_ih0,
                           const float* __restrict__ b_ih0) {
    __shared__ float xs[IN_DIM];
    int t = blockIdx.x;
    int g = threadIdx.x;
    if (g < IN_DIM) xs[g] = x[t * IN_DIM + g];
    __syncthreads();
    if (g < 300) {
        float acc = b_ih0[g];
        const float* wr = w_ih0 + g * IN_DIM;
#pragma unroll
        for (int k = 0; k < IN_DIM; k++) acc = fmaf(wr[k], xs[k], acc);
        g_gi0[t * 300 + g] = acc;
    }
}

// ---------------- main cluster kernel ----------------
__global__ void __launch_bounds__(NT, 1) __cluster_dims__(4, 1, 1)
gru_cluster_kernel(const float* __restrict__ w_hh0, const float* __restrict__ b_hh0,
                   const float* __restrict__ w_ih1, const float* __restrict__ w_hh1,
                   const float* __restrict__ b_ih1, const float* __restrict__ b_hh1,
                   const float* __restrict__ fc_w,  const float* __restrict__ fc_b,
                   float* __restrict__ out)
{
    __shared__ SmemLayout sm;
    uint32_t rank;
    asm("mov.u32 %0, %%cluster_ctarank;" : "=r"(rank));
    const int tid = threadIdx.x;

    const uint32_t a_full  = s2u(&sm.bar_full[0]);
    const uint32_t a_empty = s2u(&sm.bar_empty[0]);
    const uint32_t a_inbuf = s2u(&sm.inbuf[0][0]);
    const uint32_t a_out   = s2u(&sm.outbuf[0][0]);

    if (tid == 0) {
#pragma unroll
        for (int i = 0; i < NSLOT; i++) {
            mbar_init(a_full  + 8u * i, 1);
            mbar_init(a_empty + 8u * i, 1);
            mbar_arrive_local(a_empty + 8u * i);   // pre-grant credit (phase 0)
        }
        if (rank == R_GI) {
#pragma unroll
            for (int i = 0; i < NSLOT; i++) mbar_expect_tx(a_full + 8u * i, H_BYTES);
        } else if (rank == R_L1) {
#pragma unroll
            for (int i = 0; i < NSLOT; i++) mbar_expect_tx(a_full + 8u * i, G_BYTES);
        }
    }
    if (tid < 104) { sm.h_s[0][tid] = 0.0f; sm.h_s[1][tid] = 0.0f; }
    __syncthreads();
    cluster_sync_all();

    // warp 0 = bookkeeping (lowest arbiter priority); warps 1-7 = compute
    const int  cidx = (tid >= 32) ? (tid - 32) : 0;
    const int  idx  = (cidx < 200) ? cidx : 199;
    const int  p    = idx >> 1;          // pair id = gate row (0..99)
    const int  half = idx & 1;
    const bool lead = ((cidx & 1) == 0) && (cidx < 200) && (tid >= 32);
    const int  pos  = p + (p >= 50 ? 2 : 0);   // padded h index

    if (rank == R_L0) {
        const uint32_t rem_inbuf = mapa_u32(a_inbuf, R_GI);
        const uint32_t rem_full  = mapa_u32(a_full,  R_GI);

        if (tid < 32) {
            // ---- bookkeeping warp (warp 0) ----
            if (tid == 0) {   // certify slots for steps 0,1 (empty pre-granted ph0)
                wait_par_acq(a_empty + 0, 0);
                wait_par_acq(a_empty + 8, 0);
            }
            bar_arrive_cnt(1, NT);            // enable compute step 0
            for (int t = 0; t < T_STEPS; ++t) {
                bar_sync_cnt(2, NT);          // compute finished step t
                bar_arrive_cnt(1, NT);        // enable compute step t+1
                if (tid == 0) {
                    const int s = t & (NSLOT - 1);
                    fence_pa();
                    bulk_copy_cluster(rem_inbuf + (uint32_t)s * SLOT_B,
                                      a_out + (uint32_t)s * SLOT_B,
                                      H_BYTES, rem_full + 8u * s);
                    if (t + 2 < T_STEPS) {
                        const int sn = (t + 2) & (NSLOT - 1);
                        wait_par_acq(a_empty + 8u * sn,
                                     (uint32_t)(((t + 2) >> 3) & 1));
                    }
                }
            }
        } else {
            // ---- compute warps (1-7) ----
            u64 w0[25], w1[25], w2[25];
            load_w3(w_hh0, p, half, w0, w1, w2);
            const float bh0 = b_hh0[p], bh1 = b_hh0[p + 100], bh2 = b_hh0[p + 200];
            float gc0 = 0.f, gc1 = 0.f, gc2 = 0.f;
            if (lead) { gc0 = g_gi0[p]; gc1 = g_gi0[p + 100]; gc2 = g_gi0[p + 200]; }
            float h_prev = 0.f;

            for (int t = 0; t < T_STEPS; ++t) {
                const int s = t & (NSLOT - 1);
                bar_sync_cnt(1, NT);   // slot s certified free; h_s(t-1) visible

                float gn0 = 0.f, gn1 = 0.f, gn2 = 0.f;
                if (lead) {
                    int tn = (t + 1 < T_STEPS) ? t + 1 : t;
                    gn0 = g_gi0[tn * 300 + p];
                    gn1 = g_gi0[tn * 300 + p + 100];
                    gn2 = g_gi0[tn * 300 + p + 200];
                }
                const int buf = t & 1;
                float s0, s1, s2;
                dot3(w0, w1, w2, &sm.h_s[buf][half * 52], s0, s1, s2);
                float o0 = __shfl_down_sync(0xFFFFFFFFu, s0, 1);
                float o1 = __shfl_down_sync(0xFFFFFFFFu, s1, 1);
                float o2 = __shfl_down_sync(0xFFFFFFFFu, s2, 1);
                if (lead) {
                    float rr = sigt(gc0 + s0 + o0 + bh0);
                    float zz = sigt(gc1 + s1 + o1 + bh1);
                    float nn = tanha(gc2 + rr * (s2 + o2 + bh2));
                    float hn = nn + zz * (h_prev - nn);
                    sm.h_s[buf ^ 1][pos] = hn;
                    sm.outbuf[s][pos] = hn;
                    h_prev = hn;
                }
                gc0 = gn0; gc1 = gn1; gc2 = gn2;
                bar_arrive_cnt(2, NT);   // step t done
            }
        }
    } else if (rank == R_GI) {
        const uint32_t rem_empty_L0 = mapa_u32(a_empty, R_L0);
        const uint32_t rem_inbuf_L1 = mapa_u32(a_inbuf, R_L1);
        const uint32_t rem_full_L1  = mapa_u32(a_full,  R_L1);

        if (tid < 32) {
            if (tid == 0) {   // certify steps 0,1: data arrived + slot free
                wait_par_acq(a_full + 0, 0);
                wait_par_acq(a_full + 8, 0);
                wait_par_acq(a_empty + 0, 0);
                wait_par_acq(a_empty + 8, 0);
            }
            bar_arrive_cnt(1, NT);
            for (int t = 0; t < T_STEPS; ++t) {
                bar_sync_cnt(2, NT);
                bar_arrive_cnt(1, NT);
                if (tid == 0) {
                    const int s = t & (NSLOT - 1);
                    mbar_expect_tx(a_full + 8u * s, H_BYTES);   // re-arm consumed slot
                    arrive_rel_cluster(rem_empty_L0 + 8u * s);  // credit L0
                    fence_pa();
                    bulk_copy_cluster(rem_inbuf_L1 + (uint32_t)s * SLOT_B,
                                      a_out + (uint32_t)s * SLOT_B,
                                      G_BYTES, rem_full_L1 + 8u * s);
                    if (t + 2 < T_STEPS) {
                        const int sn = (t + 2) & (NSLOT - 1);
                        const uint32_t pn = (uint32_t)(((t + 2) >> 3) & 1);
                        wait_par_acq(a_full  + 8u * sn, pn);   // h0[t+2]
                        wait_par_acq(a_empty + 8u * sn, pn);   // L1 freed slot
                    }
                }
            }
        } else {
            u64 w0[25], w1[25], w2[25];
            load_w3(w_ih1, p, half, w0, w1, w2);
            const float bi0 = b_ih1[p], bi1 = b_ih1[p + 100], bi2 = b_ih1[p + 200];

            for (int t = 0; t < T_STEPS; ++t) {
                const int s = t & (NSLOT - 1);
                bar_sync_cnt(1, NT);   // inbuf[s] full, outbuf[s] free

                float s0, s1, s2;
                dot3(w0, w1, w2, &sm.inbuf[s][half * 52], s0, s1, s2);
                float o0 = __shfl_down_sync(0xFFFFFFFFu, s0, 1);
                float o1 = __shfl_down_sync(0xFFFFFFFFu, s1, 1);
                float o2 = __shfl_down_sync(0xFFFFFFFFu, s2, 1);
                if (lead) {
                    sm.outbuf[s][p]       = s0 + o0 + bi0;
                    sm.outbuf[s][p + 100] = s1 + o1 + bi1;
                    sm.outbuf[s][p + 200] = s2 + o2 + bi2;
                }
                bar_arrive_cnt(2, NT);
            }
        }
    } else if (rank == R_L1) {
        const uint32_t rem_empty_GI = mapa_u32(a_empty, R_GI);

        if (tid < 32) {
            if (tid == 0) {   // certify steps 0,1
                wait_par_acq(a_full + 0, 0);
                wait_par_acq(a_full + 8, 0);
            }
            bar_arrive_cnt(1, NT);
            for (int t = 0; t < T_STEPS; ++t) {
                bar_sync_cnt(2, NT);
                bar_arrive_cnt(1, NT);
                if (tid == 0) {
                    const int s = t & (NSLOT - 1);
                    mbar_expect_tx(a_full + 8u * s, G_BYTES);   // re-arm
                    arrive_rel_cluster(rem_empty_GI + 8u * s);  // credit GI
                    if (t + 2 < T_STEPS) {
                        const int sn = (t + 2) & (NSLOT - 1);
                        wait_par_acq(a_full + 8u * sn,
                                     (uint32_t)(((t + 2) >> 3) & 1));  // gi1[t+2]
                    }
                }
            }
        } else {
            u64 w0[25], w1[25], w2[25];
            load_w3(w_hh1, p, half, w0, w1, w2);
            const float bh0 = b_hh1[p], bh1 = b_hh1[p + 100], bh2 = b_hh1[p + 200];
            float h_prev = 0.f;

            for (int t = 0; t < T_STEPS; ++t) {
                const int s = t & (NSLOT - 1);
                bar_sync_cnt(1, NT);   // inbuf[s] full; h_s(t-1) visible

                // prefetch gate inputs early (hide LDS latency under dot)
                float gir = sm.inbuf[s][p];
                float giz = sm.inbuf[s][p + 100];
                float gin = sm.inbuf[s][p + 200];

                const int buf = t & 1;
                float s0, s1, s2;
                dot3(w0, w1, w2, &sm.h_s[buf][half * 52], s0, s1, s2);
                float o0 = __shfl_down_sync(0xFFFFFFFFu, s0, 1);
                float o1 = __shfl_down_sync(0xFFFFFFFFu, s1, 1);
                float o2 = __shfl_down_sync(0xFFFFFFFFu, s2, 1);
                if (lead) {
                    float rr = sigt(gir + s0 + o0 + bh0);
                    float zz = sigt(giz + s1 + o1 + bh1);
                    float nn = tanha(gin + rr * (s2 + o2 + bh2));
                    float hn = nn + zz * (h_prev - nn);
                    sm.h_s[buf ^ 1][pos] = hn;
                    h_prev = hn;
                }
                bar_arrive_cnt(2, NT);
            }
        }
        __syncthreads();
        if (tid < 100) sm.red[tid] = sm.h_s[0][tid + (tid >= 50 ? 2 : 0)] * fc_w[tid];
        __syncthreads();
        if (tid == 0) {
            float sv = fc_b[0];
            for (int j = 0; j < 100; j++) sv += sm.red[j];
            out[0] = sv;
        }
    }
    cluster_sync_all();
}

extern "C" void kernel_launch(void* const* d_in, const int* in_sizes, int n_in,
                              void* d_out, int out_size) {
    const float* x     = (const float*)d_in[0];
    const float* w_ih0 = (const float*)d_in[1];
    const float* w_hh0 = (const float*)d_in[2];
    const float* b_ih0 = (const float*)d_in[3];
    const float* b_hh0 = (const float*)d_in[4];
    const float* w_ih1 = (const float*)d_in[5];
    const float* w_hh1 = (const float*)d_in[6];
    const float* b_ih1 = (const float*)d_in[7];
    const float* b_hh1 = (const float*)d_in[8];
    const float* fc_w  = (const float*)d_in[9];
    const float* fc_b  = (const float*)d_in[10];
    float* out = (float*)d_out;

    gi0_kernel<<<T_STEPS, 320>>>(x, w_ih0, b_ih0);
    gru_cluster_kernel<<<4, NT>>>(w_hh0, b_hh0, w_ih1, w_hh1,
                                  b_ih1, b_hh1, fc_w, fc_b, out);
}

// round 14
// speedup vs baseline: 1.2045x; 1.0094x over previous
#include <cuda_runtime.h>
#include <cstdint>

// GRU_20031727468931: 2-layer GRU, T=16384, IN=14, H=100, out = FC(h2[T-1]).
// Round 14: R13 + (1) rr/zz hoisted out of the lead branch (all-lane, overlaps
// dot issue; stores untouched), (2) batched gi0 precompute (512 blocks x 32 t,
// register-resident W_ih0).

#define T_STEPS 16384
#define IN_DIM  14
#define H_DIM   100
#define NT      256    // warp 0 bookkeeping, warps 1-7 compute (200 active lanes)

#define R_L0 0
#define R_GI 1
#define R_L1 2

#define NSLOT    8
#define SLOT_F   304u                 // floats per slot (16B-aligned stride)
#define SLOT_B   (SLOT_F * 4u)        // 1216 bytes
#define H_BYTES  416u                 // 104 floats (padded h layout)
#define G_BYTES  1200u                // 300 floats

typedef unsigned long long u64;

__device__ float g_gi0[T_STEPS * 300];   // precomputed x @ W_ih0^T + b_ih0

struct __align__(16) SmemLayout {
    u64 bar_full[NSLOT];               // 64 B
    u64 bar_empty[NSLOT];              // 64 B  -> arrays below stay 16B-aligned
    alignas(16) float h_s[2][104];     // padded: value i at index i + (i>=50 ? 2 : 0)
    alignas(16) float inbuf[NSLOT][SLOT_F];
    alignas(16) float outbuf[NSLOT][SLOT_F];
    alignas(16) float red[104];
};

__device__ __forceinline__ uint32_t s2u(const void* p) {
    uint32_t a;
    asm("{.reg .u64 t; cvta.to.shared.u64 t, %1; cvt.u32.u64 %0, t;}" : "=r"(a) : "l"(p));
    return a;
}
__device__ __forceinline__ uint32_t mapa_u32(uint32_t a, uint32_t rank) {
    uint32_t r;
    asm("mapa.shared::cluster.u32 %0, %1, %2;" : "=r"(r) : "r"(a), "r"(rank));
    return r;
}
__device__ __forceinline__ void mbar_init(uint32_t a, uint32_t n) {
    asm volatile("mbarrier.init.shared.b64 [%0], %1;" :: "r"(a), "r"(n) : "memory");
}
__device__ __forceinline__ void mbar_arrive_local(uint32_t a) {
    asm volatile("mbarrier.arrive.shared.b64 _, [%0];" :: "r"(a) : "memory");
}
__device__ __forceinline__ void mbar_expect_tx(uint32_t a, uint32_t bytes) {
    asm volatile("mbarrier.arrive.expect_tx.shared.b64 _, [%0], %1;"
                 :: "r"(a), "r"(bytes) : "memory");
}
__device__ __forceinline__ void arrive_rel_cluster(uint32_t a) {
    asm volatile("mbarrier.arrive.release.cluster.shared::cluster.b64 _, [%0];"
                 :: "r"(a) : "memory");
}
// parity wait with HW-sleep suspend hint in the retry loop (no issue-slot spin)
__device__ __forceinline__ void wait_par_acq(uint32_t a, uint32_t parity) {
    asm volatile(
        "{\n\t.reg .pred P;\n"
        "W_%=:\n\t"
        "mbarrier.try_wait.parity.acquire.cluster.shared::cta.b64 P, [%0], %1, 0x989680;\n\t"
        "@!P bra W_%=;\n\t}"
        :: "r"(a), "r"(parity) : "memory");
}
__device__ __forceinline__ void fence_pa() {
    asm volatile("fence.proxy.async.shared::cta;" ::: "memory");
}
__device__ __forceinline__ void bulk_copy_cluster(uint32_t dst_dsmem, uint32_t src_local,
                                                  uint32_t bytes, uint32_t rem_mbar) {
    asm volatile(
        "cp.async.bulk.shared::cluster.shared::cta.mbarrier::complete_tx::bytes "
        "[%0], [%1], %2, [%3];"
        :: "r"(dst_dsmem), "r"(src_local), "r"(bytes), "r"(rem_mbar) : "memory");
}
__device__ __forceinline__ void bar_sync_cnt(int name, int cnt) {
    asm volatile("bar.sync %0, %1;" :: "r"(name), "r"(cnt) : "memory");
}
__device__ __forceinline__ void bar_arrive_cnt(int name, int cnt) {
    asm volatile("bar.arrive %0, %1;" :: "r"(name), "r"(cnt) : "memory");
}
__device__ __forceinline__ void fma2(u64& acc, u64 w, u64 h) {
    asm("fma.rn.f32x2 %0, %1, %2, %0;" : "+l"(acc) : "l"(w), "l"(h));
}
__device__ __forceinline__ float unpack_sum(u64 a, u64 b) {
    float l0, h0, l1, h1;
    asm("mov.b64 {%0,%1}, %2;" : "=f"(l0), "=f"(h0) : "l"(a));
    asm("mov.b64 {%0,%1}, %2;" : "=f"(l1), "=f"(h1) : "l"(b));
    return (l0 + l1) + (h0 + h1);
}
__device__ __forceinline__ float tanha(float x) {
    float y;
    asm("tanh.approx.f32 %0, %1;" : "=f"(y) : "f"(x));
    return y;
}
__device__ __forceinline__ float sigt(float x) {       // sigmoid via tanh.approx
    return fmaf(0.5f, tanha(0.5f * x), 0.5f);
}
__device__ __forceinline__ void cluster_sync_all() {
    asm volatile("barrier.cluster.arrive.aligned;" ::: "memory");
    asm volatile("barrier.cluster.wait.aligned;" ::: "memory");
}

// 3 simultaneous half-row dots sharing one h half-vector (50 floats, 16B-aligned).
__device__ __forceinline__ void dot3(const u64* __restrict__ w0,
                                     const u64* __restrict__ w1,
                                     const u64* __restrict__ w2,
                                     const float* __restrict__ hbase,
                                     float& s0, float& s1, float& s2) {
    const ulonglong2* hp = (const ulonglong2*)hbase;
    u64 a0 = 0, b0 = 0, a1 = 0, b1 = 0, a2 = 0, b2 = 0;
#pragma unroll
    for (int j = 0; j < 12; j++) {
        ulonglong2 hv = hp[j];
        fma2(a0, w0[2 * j], hv.x);  fma2(b0, w0[2 * j + 1], hv.y);
        fma2(a1, w1[2 * j], hv.x);  fma2(b1, w1[2 * j + 1], hv.y);
        fma2(a2, w2[2 * j], hv.x);  fma2(b2, w2[2 * j + 1], hv.y);
    }
    u64 htail = ((const u64*)hbase)[24];
    fma2(a0, w0[24], htail);
    fma2(a1, w1[24], htail);
    fma2(a2, w2[24], htail);
    s0 = unpack_sum(a0, b0);
    s1 = unpack_sum(a1, b1);
    s2 = unpack_sum(a2, b2);
}

__device__ __forceinline__ void load_w3(const float* __restrict__ W, int p, int half,
                                        u64* w0, u64* w1, u64* w2) {
    const u64* g0 = (const u64*)(W + (p)       * H_DIM + half * 50);
    const u64* g1 = (const u64*)(W + (p + 100) * H_DIM + half * 50);
    const u64* g2 = (const u64*)(W + (p + 200) * H_DIM + half * 50);
#pragma unroll
    for (int j = 0; j < 25; j++) { w0[j] = g0[j]; w1[j] = g1[j]; w2[j] = g2[j]; }
}

// ---------------- precompute: gi0[t][g] = x[t]·W_ih0[g] + b_ih0[g] ----------------
// Batched: each block handles 32 timesteps with register-resident weights.
#define GI0_TS 32
__global__ void gi0_kernel(const float* __restrict__ x,
                           const float* __restrict__ w_ih0,
                           const float* __restrict__ b_ih0) {
    __shared__ float xs[GI0_TS][IN_DIM];
    const int t0 = blockIdx.x * GI0_TS;
    const int g = threadIdx.x;
    for (int i = g; i < GI0_TS * IN_DIM; i += 320)
        xs[i / IN_DIM][i % IN_DIM] = x[t0 * IN_DIM + i];
    __syncthreads();
    if (g < 300) {
        float w[IN_DIM];
        const float* wr = w_ih0 + g * IN_DIM;
#pragma unroll
        for (int k = 0; k < IN_DIM; k++) w[k] = wr[k];
        const float b = b_ih0[g];
#pragma unroll 4
        for (int tt = 0; tt < GI0_TS; tt++) {
            float acc = b;
#pragma unroll
            for (int k = 0; k < IN_DIM; k++) acc = fmaf(w[k], xs[tt][k], acc);
            g_gi0[(t0 + tt) * 300 + g] = acc;
        }
    }
}

// ---------------- main cluster kernel ----------------
__global__ void __launch_bounds__(NT, 1) __cluster_dims__(4, 1, 1)
gru_cluster_kernel(const float* __restrict__ w_hh0, const float* __restrict__ b_hh0,
                   const float* __restrict__ w_ih1, const float* __restrict__ w_hh1,
                   const float* __restrict__ b_ih1, const float* __restrict__ b_hh1,
                   const float* __restrict__ fc_w,  const float* __restrict__ fc_b,
                   float* __restrict__ out)
{
    __shared__ SmemLayout sm;
    uint32_t rank;
    asm("mov.u32 %0, %%cluster_ctarank;" : "=r"(rank));
    const int tid = threadIdx.x;

    const uint32_t a_full  = s2u(&sm.bar_full[0]);
    const uint32_t a_empty = s2u(&sm.bar_empty[0]);
    const uint32_t a_inbuf = s2u(&sm.inbuf[0][0]);
    const uint32_t a_out   = s2u(&sm.outbuf[0][0]);

    if (tid == 0) {
#pragma unroll
        for (int i = 0; i < NSLOT; i++) {
            mbar_init(a_full  + 8u * i, 1);
            mbar_init(a_empty + 8u * i, 1);
            mbar_arrive_local(a_empty + 8u * i);   // pre-grant credit (phase 0)
        }
        if (rank == R_GI) {
#pragma unroll
            for (int i = 0; i < NSLOT; i++) mbar_expect_tx(a_full + 8u * i, H_BYTES);
        } else if (rank == R_L1) {
#pragma unroll
            for (int i = 0; i < NSLOT; i++) mbar_expect_tx(a_full + 8u * i, G_BYTES);
        }
    }
    if (tid < 104) { sm.h_s[0][tid] = 0.0f; sm.h_s[1][tid] = 0.0f; }
    __syncthreads();
    cluster_sync_all();

    // warp 0 = bookkeeping (lowest arbiter priority); warps 1-7 = compute
    const int  cidx = (tid >= 32) ? (tid - 32) : 0;
    const int  idx  = (cidx < 200) ? cidx : 199;
    const int  p    = idx >> 1;          // pair id = gate row (0..99)
    const int  half = idx & 1;
    const bool lead = ((cidx & 1) == 0) && (cidx < 200) && (tid >= 32);
    const int  pos  = p + (p >= 50 ? 2 : 0);   // padded h index

    if (rank == R_L0) {
        const uint32_t rem_inbuf = mapa_u32(a_inbuf, R_GI);
        const uint32_t rem_full  = mapa_u32(a_full,  R_GI);

        if (tid < 32) {
            // ---- bookkeeping warp (warp 0) ----
            if (tid == 0) {   // certify slots for steps 0,1 (empty pre-granted ph0)
                wait_par_acq(a_empty + 0, 0);
                wait_par_acq(a_empty + 8, 0);
            }
            bar_arrive_cnt(1, NT);            // enable compute step 0
            for (int t = 0; t < T_STEPS; ++t) {
                bar_sync_cnt(2, NT);          // compute finished step t
                bar_arrive_cnt(1, NT);        // enable compute step t+1
                if (tid == 0) {
                    const int s = t & (NSLOT - 1);
                    fence_pa();
                    bulk_copy_cluster(rem_inbuf + (uint32_t)s * SLOT_B,
                                      a_out + (uint32_t)s * SLOT_B,
                                      H_BYTES, rem_full + 8u * s);
                    if (t + 2 < T_STEPS) {
                        const int sn = (t + 2) & (NSLOT - 1);
                        wait_par_acq(a_empty + 8u * sn,
                                     (uint32_t)(((t + 2) >> 3) & 1));
                    }
                }
            }
        } else {
            // ---- compute warps (1-7) ----
            u64 w0[25], w1[25], w2[25];
            load_w3(w_hh0, p, half, w0, w1, w2);
            const float bh0 = b_hh0[p], bh1 = b_hh0[p + 100], bh2 = b_hh0[p + 200];
            float gc0 = 0.f, gc1 = 0.f, gc2 = 0.f;
            if (lead) { gc0 = g_gi0[p]; gc1 = g_gi0[p + 100]; gc2 = g_gi0[p + 200]; }
            float h_prev = 0.f;

            for (int t = 0; t < T_STEPS; ++t) {
                const int s = t & (NSLOT - 1);
                bar_sync_cnt(1, NT);   // slot s certified free; h_s(t-1) visible

                float gn0 = 0.f, gn1 = 0.f, gn2 = 0.f;
                if (lead) {
                    int tn = (t + 1 < T_STEPS) ? t + 1 : t;
                    gn0 = g_gi0[tn * 300 + p];
                    gn1 = g_gi0[tn * 300 + p + 100];
                    gn2 = g_gi0[tn * 300 + p + 200];
                }
                const int buf = t & 1;
                float s0, s1, s2;
                dot3(w0, w1, w2, &sm.h_s[buf][half * 52], s0, s1, s2);
                float o0 = __shfl_down_sync(0xFFFFFFFFu, s0, 1);
                float o1 = __shfl_down_sync(0xFFFFFFFFu, s1, 1);
                float o2 = __shfl_down_sync(0xFFFFFFFFu, s2, 1);

                // rr/zz hoisted out of the lead branch: their 60-cyc chains
                // overlap issue; non-lead lanes compute harmless finite garbage.
                float rr = sigt(gc0 + s0 + o0 + bh0);
                float zz = sigt(gc1 + s1 + o1 + bh1);
                if (lead) {
                    float nn = tanha(gc2 + rr * (s2 + o2 + bh2));
                    float hn = nn + zz * (h_prev - nn);
                    sm.h_s[buf ^ 1][pos] = hn;
                    sm.outbuf[s][pos] = hn;
                    h_prev = hn;
                }
                gc0 = gn0; gc1 = gn1; gc2 = gn2;
                bar_arrive_cnt(2, NT);   // step t done
            }
        }
    } else if (rank == R_GI) {
        const uint32_t rem_empty_L0 = mapa_u32(a_empty, R_L0);
        const uint32_t rem_inbuf_L1 = mapa_u32(a_inbuf, R_L1);
        const uint32_t rem_full_L1  = mapa_u32(a_full,  R_L1);

        if (tid < 32) {
            if (tid == 0) {   // certify steps 0,1: data arrived + slot free
                wait_par_acq(a_full + 0, 0);
                wait_par_acq(a_full + 8, 0);
                wait_par_acq(a_empty + 0, 0);
                wait_par_acq(a_empty + 8, 0);
            }
            bar_arrive_cnt(1, NT);
            for (int t = 0; t < T_STEPS; ++t) {
                bar_sync_cnt(2, NT);
                bar_arrive_cnt(1, NT);
                if (tid == 0) {
                    const int s = t & (NSLOT - 1);
                    mbar_expect_tx(a_full + 8u * s, H_BYTES);   // re-arm consumed slot
                    arrive_rel_cluster(rem_empty_L0 + 8u * s);  // credit L0
                    fence_pa();
                    bulk_copy_cluster(rem_inbuf_L1 + (uint32_t)s * SLOT_B,
                                      a_out + (uint32_t)s * SLOT_B,
                                      G_BYTES, rem_full_L1 + 8u * s);
                    if (t + 2 < T_STEPS) {
                        const int sn = (t + 2) & (NSLOT - 1);
                        const uint32_t pn = (uint32_t)(((t + 2) >> 3) & 1);
                        wait_par_acq(a_full  + 8u * sn, pn);   // h0[t+2]
                        wait_par_acq(a_empty + 8u * sn, pn);   // L1 freed slot
                    }
                }
            }
        } else {
            u64 w0[25], w1[25], w2[25];
            load_w3(w_ih1, p, half, w0, w1, w2);
            const float bi0 = b_ih1[p], bi1 = b_ih1[p + 100], bi2 = b_ih1[p + 200];

            for (int t = 0; t < T_STEPS; ++t) {
                const int s = t & (NSLOT - 1);
                bar_sync_cnt(1, NT);   // inbuf[s] full, outbuf[s] free

                float s0, s1, s2;
                dot3(w0, w1, w2, &sm.inbuf[s][half * 52], s0, s1, s2);
                float o0 = __shfl_down_sync(0xFFFFFFFFu, s0, 1);
                float o1 = __shfl_down_sync(0xFFFFFFFFu, s1, 1);
                float o2 = __shfl_down_sync(0xFFFFFFFFu, s2, 1);
                if (lead) {
                    sm.outbuf[s][p]       = s0 + o0 + bi0;
                    sm.outbuf[s][p + 100] = s1 + o1 + bi1;
                    sm.outbuf[s][p + 200] = s2 + o2 + bi2;
                }
                bar_arrive_cnt(2, NT);
            }
        }
    } else if (rank == R_L1) {
        const uint32_t rem_empty_GI = mapa_u32(a_empty, R_GI);

        if (tid < 32) {
            if (tid == 0) {   // certify steps 0,1
                wait_par_acq(a_full + 0, 0);
                wait_par_acq(a_full + 8, 0);
            }
            bar_arrive_cnt(1, NT);
            for (int t = 0; t < T_STEPS; ++t) {
                bar_sync_cnt(2, NT);
                bar_arrive_cnt(1, NT);
                if (tid == 0) {
                    const int s = t & (NSLOT - 1);
                    mbar_expect_tx(a_full + 8u * s, G_BYTES);   // re-arm
                    arrive_rel_cluster(rem_empty_GI + 8u * s);  // credit GI
                    if (t + 2 < T_STEPS) {
                        const int sn = (t + 2) & (NSLOT - 1);
                        wait_par_acq(a_full + 8u * sn,
                                     (uint32_t)(((t + 2) >> 3) & 1));  // gi1[t+2]
                    }
                }
            }
        } else {
            u64 w0[25], w1[25], w2[25];
            load_w3(w_hh1, p, half, w0, w1, w2);
            const float bh0 = b_hh1[p], bh1 = b_hh1[p + 100], bh2 = b_hh1[p + 200];
            float h_prev = 0.f;

            for (int t = 0; t < T_STEPS; ++t) {
                const int s = t & (NSLOT - 1);
                bar_sync_cnt(1, NT);   // inbuf[s] full; h_s(t-1) visible

                // prefetch gate inputs early (hide LDS latency under dot)
                float gir = sm.inbuf[s][p];
                float giz = sm.inbuf[s][p + 100];
                float gin = sm.inbuf[s][p + 200];

                const int buf = t & 1;
                float s0, s1, s2;
                dot3(w0, w1, w2, &sm.h_s[buf][half * 52], s0, s1, s2);
                float o0 = __shfl_down_sync(0xFFFFFFFFu, s0, 1);
                float o1 = __shfl_down_sync(0xFFFFFFFFu, s1, 1);
                float o2 = __shfl_down_sync(0xFFFFFFFFu, s2, 1);

                // rr/zz hoisted out of the lead branch (exact in all lanes here)
                float rr = sigt(gir + s0 + o0 + bh0);
                float zz = sigt(giz + s1 + o1 + bh1);
                if (lead) {
                    float nn = tanha(gin + rr * (s2 + o2 + bh2));
                    float hn = nn + zz * (h_prev - nn);
                    sm.h_s[buf ^ 1][pos] = hn;
                    h_prev = hn;
                }
                bar_arrive_cnt(2, NT);
            }
        }
        __syncthreads();
        if (tid < 100) sm.red[tid] = sm.h_s[0][tid + (tid >= 50 ? 2 : 0)] * fc_w[tid];
        __syncthreads();
        if (tid == 0) {
            float sv = fc_b[0];
            for (int j = 0; j < 100; j++) sv += sm.red[j];
            out[0] = sv;
        }
    }
    cluster_sync_all();
}

extern "C" void kernel_launch(void* const* d_in, const int* in_sizes, int n_in,
                              void* d_out, int out_size) {
    const float* x     = (const float*)d_in[0];
    const float* w_ih0 = (const float*)d_in[1];
    const float* w_hh0 = (const float*)d_in[2];
    const float* b_ih0 = (const float*)d_in[3];
    const float* b_hh0 = (const float*)d_in[4];
    const float* w_ih1 = (const float*)d_in[5];
    const float* w_hh1 = (const float*)d_in[6];
    const float* b_ih1 = (const float*)d_in[7];
    const float* b_hh1 = (const float*)d_in[8];
    const float* fc_w  = (const float*)d_in[9];
    const float* fc_b  = (const float*)d_in[10];
    float* out = (float*)d_out;

    gi0_kernel<<<T_STEPS / GI0_TS, 320>>>(x, w_ih0, b_ih0);
    gru_cluster_kernel<<<4, NT>>>(w_hh0, b_hh0, w_ih1, w_hh1,
                                  b_ih1, b_hh1, fc_w, fc_b, out);
}

// round 15
// speedup vs baseline: 1.2260x; 1.0178x over previous
#include <cuda_runtime.h>
#include <cstdint>

// GRU_20031727468931: 2-layer GRU, T=16384, IN=14, H=100, out = FC(h2[T-1]).
// Round 15: R14 + b_hh r/z bias folding into off-path prefetches (L0: folded at
// gi0 prefetch; L1: folded right after the early inbuf LDS). bh2 stays inside
// the r*(h_n+b_hh_n) term (not foldable). Everything else identical to R14.

#define T_STEPS 16384
#define IN_DIM  14
#define H_DIM   100
#define NT      256    // warp 0 bookkeeping, warps 1-7 compute (200 active lanes)

#define R_L0 0
#define R_GI 1
#define R_L1 2

#define NSLOT    8
#define SLOT_F   304u                 // floats per slot (16B-aligned stride)
#define SLOT_B   (SLOT_F * 4u)        // 1216 bytes
#define H_BYTES  416u                 // 104 floats (padded h layout)
#define G_BYTES  1200u                // 300 floats

typedef unsigned long long u64;

__device__ float g_gi0[T_STEPS * 300];   // precomputed x @ W_ih0^T + b_ih0

struct __align__(16) SmemLayout {
    u64 bar_full[NSLOT];               // 64 B
    u64 bar_empty[NSLOT];              // 64 B  -> arrays below stay 16B-aligned
    alignas(16) float h_s[2][104];     // padded: value i at index i + (i>=50 ? 2 : 0)
    alignas(16) float inbuf[NSLOT][SLOT_F];
    alignas(16) float outbuf[NSLOT][SLOT_F];
    alignas(16) float red[104];
};

__device__ __forceinline__ uint32_t s2u(const void* p) {
    uint32_t a;
    asm("{.reg .u64 t; cvta.to.shared.u64 t, %1; cvt.u32.u64 %0, t;}" : "=r"(a) : "l"(p));
    return a;
}
__device__ __forceinline__ uint32_t mapa_u32(uint32_t a, uint32_t rank) {
    uint32_t r;
    asm("mapa.shared::cluster.u32 %0, %1, %2;" : "=r"(r) : "r"(a), "r"(rank));
    return r;
}
__device__ __forceinline__ void mbar_init(uint32_t a, uint32_t n) {
    asm volatile("mbarrier.init.shared.b64 [%0], %1;" :: "r"(a), "r"(n) : "memory");
}
__device__ __forceinline__ void mbar_arrive_local(uint32_t a) {
    asm volatile("mbarrier.arrive.shared.b64 _, [%0];" :: "r"(a) : "memory");
}
__device__ __forceinline__ void mbar_expect_tx(uint32_t a, uint32_t bytes) {
    asm volatile("mbarrier.arrive.expect_tx.shared.b64 _, [%0], %1;"
                 :: "r"(a), "r"(bytes) : "memory");
}
__device__ __forceinline__ void arrive_rel_cluster(uint32_t a) {
    asm volatile("mbarrier.arrive.release.cluster.shared::cluster.b64 _, [%0];"
                 :: "r"(a) : "memory");
}
// parity wait with HW-sleep suspend hint in the retry loop (no issue-slot spin)
__device__ __forceinline__ void wait_par_acq(uint32_t a, uint32_t parity) {
    asm volatile(
        "{\n\t.reg .pred P;\n"
        "W_%=:\n\t"
        "mbarrier.try_wait.parity.acquire.cluster.shared::cta.b64 P, [%0], %1, 0x989680;\n\t"
        "@!P bra W_%=;\n\t}"
        :: "r"(a), "r"(parity) : "memory");
}
__device__ __forceinline__ void fence_pa() {
    asm volatile("fence.proxy.async.shared::cta;" ::: "memory");
}
__device__ __forceinline__ void bulk_copy_cluster(uint32_t dst_dsmem, uint32_t src_local,
                                                  uint32_t bytes, uint32_t rem_mbar) {
    asm volatile(
        "cp.async.bulk.shared::cluster.shared::cta.mbarrier::complete_tx::bytes "
        "[%0], [%1], %2, [%3];"
        :: "r"(dst_dsmem), "r"(src_local), "r"(bytes), "r"(rem_mbar) : "memory");
}
__device__ __forceinline__ void bar_sync_cnt(int name, int cnt) {
    asm volatile("bar.sync %0, %1;" :: "r"(name), "r"(cnt) : "memory");
}
__device__ __forceinline__ void bar_arrive_cnt(int name, int cnt) {
    asm volatile("bar.arrive %0, %1;" :: "r"(name), "r"(cnt) : "memory");
}
__device__ __forceinline__ void fma2(u64& acc, u64 w, u64 h) {
    asm("fma.rn.f32x2 %0, %1, %2, %0;" : "+l"(acc) : "l"(w), "l"(h));
}
__device__ __forceinline__ float unpack_sum(u64 a, u64 b) {
    float l0, h0, l1, h1;
    asm("mov.b64 {%0,%1}, %2;" : "=f"(l0), "=f"(h0) : "l"(a));
    asm("mov.b64 {%0,%1}, %2;" : "=f"(l1), "=f"(h1) : "l"(b));
    return (l0 + l1) + (h0 + h1);
}
__device__ __forceinline__ float tanha(float x) {
    float y;
    asm("tanh.approx.f32 %0, %1;" : "=f"(y) : "f"(x));
    return y;
}
__device__ __forceinline__ float sigt(float x) {       // sigmoid via tanh.approx
    return fmaf(0.5f, tanha(0.5f * x), 0.5f);
}
__device__ __forceinline__ void cluster_sync_all() {
    asm volatile("barrier.cluster.arrive.aligned;" ::: "memory");
    asm volatile("barrier.cluster.wait.aligned;" ::: "memory");
}

// 3 simultaneous half-row dots sharing one h half-vector (50 floats, 16B-aligned).
__device__ __forceinline__ void dot3(const u64* __restrict__ w0,
                                     const u64* __restrict__ w1,
                                     const u64* __restrict__ w2,
                                     const float* __restrict__ hbase,
                                     float& s0, float& s1, float& s2) {
    const ulonglong2* hp = (const ulonglong2*)hbase;
    u64 a0 = 0, b0 = 0, a1 = 0, b1 = 0, a2 = 0, b2 = 0;
#pragma unroll
    for (int j = 0; j < 12; j++) {
        ulonglong2 hv = hp[j];
        fma2(a0, w0[2 * j], hv.x);  fma2(b0, w0[2 * j + 1], hv.y);
        fma2(a1, w1[2 * j], hv.x);  fma2(b1, w1[2 * j + 1], hv.y);
        fma2(a2, w2[2 * j], hv.x);  fma2(b2, w2[2 * j + 1], hv.y);
    }
    u64 htail = ((const u64*)hbase)[24];
    fma2(a0, w0[24], htail);
    fma2(a1, w1[24], htail);
    fma2(a2, w2[24], htail);
    s0 = unpack_sum(a0, b0);
    s1 = unpack_sum(a1, b1);
    s2 = unpack_sum(a2, b2);
}

__device__ __forceinline__ void load_w3(const float* __restrict__ W, int p, int half,
                                        u64* w0, u64* w1, u64* w2) {
    const u64* g0 = (const u64*)(W + (p)       * H_DIM + half * 50);
    const u64* g1 = (const u64*)(W + (p + 100) * H_DIM + half * 50);
    const u64* g2 = (const u64*)(W + (p + 200) * H_DIM + half * 50);
#pragma unroll
    for (int j = 0; j < 25; j++) { w0[j] = g0[j]; w1[j] = g1[j]; w2[j] = g2[j]; }
}

// ---------------- precompute: gi0[t][g] = x[t]·W_ih0[g] + b_ih0[g] ----------------
// Batched: each block handles 32 timesteps with register-resident weights.
#define GI0_TS 32
__global__ void gi0_kernel(const float* __restrict__ x,
                           const float* __restrict__ w_ih0,
                           const float* __restrict__ b_ih0) {
    __shared__ float xs[GI0_TS][IN_DIM];
    const int t0 = blockIdx.x * GI0_TS;
    const int g = threadIdx.x;
    for (int i = g; i < GI0_TS * IN_DIM; i += 320)
        xs[i / IN_DIM][i % IN_DIM] = x[t0 * IN_DIM + i];
    __syncthreads();
    if (g < 300) {
        float w[IN_DIM];
        const float* wr = w_ih0 + g * IN_DIM;
#pragma unroll
        for (int k = 0; k < IN_DIM; k++) w[k] = wr[k];
        const float b = b_ih0[g];
#pragma unroll 4
        for (int tt = 0; tt < GI0_TS; tt++) {
            float acc = b;
#pragma unroll
            for (int k = 0; k < IN_DIM; k++) acc = fmaf(w[k], xs[tt][k], acc);
            g_gi0[(t0 + tt) * 300 + g] = acc;
        }
    }
}

// ---------------- main cluster kernel ----------------
__global__ void __launch_bounds__(NT, 1) __cluster_dims__(4, 1, 1)
gru_cluster_kernel(const float* __restrict__ w_hh0, const float* __restrict__ b_hh0,
                   const float* __restrict__ w_ih1, const float* __restrict__ w_hh1,
                   const float* __restrict__ b_ih1, const float* __restrict__ b_hh1,
                   const float* __restrict__ fc_w,  const float* __restrict__ fc_b,
                   float* __restrict__ out)
{
    __shared__ SmemLayout sm;
    uint32_t rank;
    asm("mov.u32 %0, %%cluster_ctarank;" : "=r"(rank));
    const int tid = threadIdx.x;

    const uint32_t a_full  = s2u(&sm.bar_full[0]);
    const uint32_t a_empty = s2u(&sm.bar_empty[0]);
    const uint32_t a_inbuf = s2u(&sm.inbuf[0][0]);
    const uint32_t a_out   = s2u(&sm.outbuf[0][0]);

    if (tid == 0) {
#pragma unroll
        for (int i = 0; i < NSLOT; i++) {
            mbar_init(a_full  + 8u * i, 1);
            mbar_init(a_empty + 8u * i, 1);
            mbar_arrive_local(a_empty + 8u * i);   // pre-grant credit (phase 0)
        }
        if (rank == R_GI) {
#pragma unroll
            for (int i = 0; i < NSLOT; i++) mbar_expect_tx(a_full + 8u * i, H_BYTES);
        } else if (rank == R_L1) {
#pragma unroll
            for (int i = 0; i < NSLOT; i++) mbar_expect_tx(a_full + 8u * i, G_BYTES);
        }
    }
    if (tid < 104) { sm.h_s[0][tid] = 0.0f; sm.h_s[1][tid] = 0.0f; }
    __syncthreads();
    cluster_sync_all();

    // warp 0 = bookkeeping (lowest arbiter priority); warps 1-7 = compute
    const int  cidx = (tid >= 32) ? (tid - 32) : 0;
    const int  idx  = (cidx < 200) ? cidx : 199;
    const int  p    = idx >> 1;          // pair id = gate row (0..99)
    const int  half = idx & 1;
    const bool lead = ((cidx & 1) == 0) && (cidx < 200) && (tid >= 32);
    const int  pos  = p + (p >= 50 ? 2 : 0);   // padded h index

    if (rank == R_L0) {
        const uint32_t rem_inbuf = mapa_u32(a_inbuf, R_GI);
        const uint32_t rem_full  = mapa_u32(a_full,  R_GI);

        if (tid < 32) {
            // ---- bookkeeping warp (warp 0) ----
            if (tid == 0) {   // certify slots for steps 0,1 (empty pre-granted ph0)
                wait_par_acq(a_empty + 0, 0);
                wait_par_acq(a_empty + 8, 0);
            }
            bar_arrive_cnt(1, NT);            // enable compute step 0
            for (int t = 0; t < T_STEPS; ++t) {
                bar_sync_cnt(2, NT);          // compute finished step t
                bar_arrive_cnt(1, NT);        // enable compute step t+1
                if (tid == 0) {
                    const int s = t & (NSLOT - 1);
                    fence_pa();
                    bulk_copy_cluster(rem_inbuf + (uint32_t)s * SLOT_B,
                                      a_out + (uint32_t)s * SLOT_B,
                                      H_BYTES, rem_full + 8u * s);
                    if (t + 2 < T_STEPS) {   // 2-step look-ahead certification
                        const int sn = (t + 2) & (NSLOT - 1);
                        wait_par_acq(a_empty + 8u * sn,
                                     (uint32_t)(((t + 2) >> 3) & 1));
                    }
                }
            }
        } else {
            // ---- compute warps (1-7) ----
            u64 w0[25], w1[25], w2[25];
            load_w3(w_hh0, p, half, w0, w1, w2);
            const float bh0 = b_hh0[p], bh1 = b_hh0[p + 100], bh2 = b_hh0[p + 200];
            // bh0/bh1 folded into the prefetched gi values (off-path adds)
            float gc0 = 0.f, gc1 = 0.f, gc2 = 0.f;
            if (lead) {
                gc0 = g_gi0[p]       + bh0;
                gc1 = g_gi0[p + 100] + bh1;
                gc2 = g_gi0[p + 200];
            }
            float h_prev = 0.f;

            for (int t = 0; t < T_STEPS; ++t) {
                const int s = t & (NSLOT - 1);
                bar_sync_cnt(1, NT);   // slot s certified free; h_s(t-1) visible

                float gn0 = 0.f, gn1 = 0.f, gn2 = 0.f;
                if (lead) {
                    int tn = (t + 1 < T_STEPS) ? t + 1 : t;
                    gn0 = g_gi0[tn * 300 + p]       + bh0;   // fold bias off-path
                    gn1 = g_gi0[tn * 300 + p + 100] + bh1;
                    gn2 = g_gi0[tn * 300 + p + 200];
                }
                const int buf = t & 1;
                float s0, s1, s2;
                dot3(w0, w1, w2, &sm.h_s[buf][half * 52], s0, s1, s2);
                float o0 = __shfl_down_sync(0xFFFFFFFFu, s0, 1);
                float o1 = __shfl_down_sync(0xFFFFFFFFu, s1, 1);
                float o2 = __shfl_down_sync(0xFFFFFFFFu, s2, 1);

                // rr/zz all-lane (overlap issue); biases pre-folded into gc0/gc1
                float rr = sigt(gc0 + s0 + o0);
                float zz = sigt(gc1 + s1 + o1);
                if (lead) {
                    float nn = tanha(gc2 + rr * (s2 + o2 + bh2));
                    float hn = nn + zz * (h_prev - nn);
                    sm.h_s[buf ^ 1][pos] = hn;
                    sm.outbuf[s][pos] = hn;
                    h_prev = hn;
                }
                gc0 = gn0; gc1 = gn1; gc2 = gn2;
                bar_arrive_cnt(2, NT);   // step t done
            }
        }
    } else if (rank == R_GI) {
        const uint32_t rem_empty_L0 = mapa_u32(a_empty, R_L0);
        const uint32_t rem_inbuf_L1 = mapa_u32(a_inbuf, R_L1);
        const uint32_t rem_full_L1  = mapa_u32(a_full,  R_L1);

        if (tid < 32) {
            if (tid == 0) {   // certify steps 0,1: data arrived + slot free
                wait_par_acq(a_full + 0, 0);
                wait_par_acq(a_full + 8, 0);
                wait_par_acq(a_empty + 0, 0);
                wait_par_acq(a_empty + 8, 0);
            }
            bar_arrive_cnt(1, NT);
            for (int t = 0; t < T_STEPS; ++t) {
                bar_sync_cnt(2, NT);
                bar_arrive_cnt(1, NT);
                if (tid == 0) {
                    const int s = t & (NSLOT - 1);
                    mbar_expect_tx(a_full + 8u * s, H_BYTES);   // re-arm consumed slot
                    arrive_rel_cluster(rem_empty_L0 + 8u * s);  // credit L0
                    fence_pa();
                    bulk_copy_cluster(rem_inbuf_L1 + (uint32_t)s * SLOT_B,
                                      a_out + (uint32_t)s * SLOT_B,
                                      G_BYTES, rem_full_L1 + 8u * s);
                    if (t + 2 < T_STEPS) {   // 2-step look-ahead certification
                        const int sn = (t + 2) & (NSLOT - 1);
                        const uint32_t pn = (uint32_t)(((t + 2) >> 3) & 1);
                        wait_par_acq(a_full  + 8u * sn, pn);   // h0[t+2]
                        wait_par_acq(a_empty + 8u * sn, pn);   // L1 freed slot
                    }
                }
            }
        } else {
            u64 w0[25], w1[25], w2[25];
            load_w3(w_ih1, p, half, w0, w1, w2);
            const float bi0 = b_ih1[p], bi1 = b_ih1[p + 100], bi2 = b_ih1[p + 200];

            for (int t = 0; t < T_STEPS; ++t) {
                const int s = t & (NSLOT - 1);
                bar_sync_cnt(1, NT);   // inbuf[s] full, outbuf[s] free

                float s0, s1, s2;
                dot3(w0, w1, w2, &sm.inbuf[s][half * 52], s0, s1, s2);
                float o0 = __shfl_down_sync(0xFFFFFFFFu, s0, 1);
                float o1 = __shfl_down_sync(0xFFFFFFFFu, s1, 1);
                float o2 = __shfl_down_sync(0xFFFFFFFFu, s2, 1);
                if (lead) {
                    sm.outbuf[s][p]       = s0 + o0 + bi0;
                    sm.outbuf[s][p + 100] = s1 + o1 + bi1;
                    sm.outbuf[s][p + 200] = s2 + o2 + bi2;
                }
                bar_arrive_cnt(2, NT);
            }
        }
    } else if (rank == R_L1) {
        const uint32_t rem_empty_GI = mapa_u32(a_empty, R_GI);

        if (tid < 32) {
            if (tid == 0) {   // certify steps 0,1
                wait_par_acq(a_full + 0, 0);
                wait_par_acq(a_full + 8, 0);
            }
            bar_arrive_cnt(1, NT);
            for (int t = 0; t < T_STEPS; ++t) {
                bar_sync_cnt(2, NT);
                bar_arrive_cnt(1, NT);
                if (tid == 0) {
                    const int s = t & (NSLOT - 1);
                    mbar_expect_tx(a_full + 8u * s, G_BYTES);   // re-arm
                    arrive_rel_cluster(rem_empty_GI + 8u * s);  // credit GI
                    if (t + 2 < T_STEPS) {
                        const int sn = (t + 2) & (NSLOT - 1);
                        wait_par_acq(a_full + 8u * sn,
                                     (uint32_t)(((t + 2) >> 3) & 1));  // gi1[t+2]
                    }
                }
            }
        } else {
            u64 w0[25], w1[25], w2[25];
            load_w3(w_hh1, p, half, w0, w1, w2);
            const float bh0 = b_hh1[p], bh1 = b_hh1[p + 100], bh2 = b_hh1[p + 200];
            float h_prev = 0.f;

            for (int t = 0; t < T_STEPS; ++t) {
                const int s = t & (NSLOT - 1);
                bar_sync_cnt(1, NT);   // inbuf[s] full; h_s(t-1) visible

                // prefetch gate inputs early; fold r/z recurrent biases here
                float gir = sm.inbuf[s][p]       + bh0;
                float giz = sm.inbuf[s][p + 100] + bh1;
                float gin = sm.inbuf[s][p + 200];

                const int buf = t & 1;
                float s0, s1, s2;
                dot3(w0, w1, w2, &sm.h_s[buf][half * 52], s0, s1, s2);
                float o0 = __shfl_down_sync(0xFFFFFFFFu, s0, 1);
                float o1 = __shfl_down_sync(0xFFFFFFFFu, s1, 1);
                float o2 = __shfl_down_sync(0xFFFFFFFFu, s2, 1);

                float rr = sigt(gir + s0 + o0);
                float zz = sigt(giz + s1 + o1);
                if (lead) {
                    float nn = tanha(gin + rr * (s2 + o2 + bh2));
                    float hn = nn + zz * (h_prev - nn);
                    sm.h_s[buf ^ 1][pos] = hn;
                    h_prev = hn;
                }
                bar_arrive_cnt(2, NT);
            }
        }
        __syncthreads();
        if (tid < 100) sm.red[tid] = sm.h_s[0][tid + (tid >= 50 ? 2 : 0)] * fc_w[tid];
        __syncthreads();
        if (tid == 0) {
            float sv = fc_b[0];
            for (int j = 0; j < 100; j++) sv += sm.red[j];
            out[0] = sv;
        }
    }
    cluster_sync_all();
}

extern "C" void kernel_launch(void* const* d_in, const int* in_sizes, int n_in,
                              void* d_out, int out_size) {
    const float* x     = (const float*)d_in[0];
    const float* w_ih0 = (const float*)d_in[1];
    const float* w_hh0 = (const float*)d_in[2];
    const float* b_ih0 = (const float*)d_in[3];
    const float* b_hh0 = (const float*)d_in[4];
    const float* w_ih1 = (const float*)d_in[5];
    const float* w_hh1 = (const float*)d_in[6];
    const float* b_ih1 = (const float*)d_in[7];
    const float* b_hh1 = (const float*)d_in[8];
    const float* fc_w  = (const float*)d_in[9];
    const float* fc_b  = (const float*)d_in[10];
    float* out = (float*)d_out;

    gi0_kernel<<<T_STEPS / GI0_TS, 320>>>(x, w_ih0, b_ih0);
    gru_cluster_kernel<<<4, NT>>>(w_hh0, b_hh0, w_ih1, w_hh1,
                                  b_ih1, b_hh1, fc_w, fc_b, out);
}